// round 16
// baseline (speedup 1.0000x reference)
#include <cuda_runtime.h>
#include <cuda_bf16.h>
#include <math.h>
#include <stdint.h>

#define NNODES 8192
#define EEDGES 262144
#define INC    256
#define HH     8
#define CC     32
#define HCC    256
#define OUTC   32
#define FLAT   (NNODES * HCC)
#define NGEMVB 512
#define NEG    0.2f

// ---- scratch (device globals; zero-initialized at module load) ----
__device__ float g_xh[NNODES * HCC];          // fp32 projected features (attn)
__device__ unsigned g_xhb[NNODES * (HCC/2)];  // bf16x2 packed copy (aggregation)
__device__ float g_asrc[NNODES * HH];
__device__ float g_adst[NNODES * HH];
__device__ int   g_deg[NNODES];
__device__ int   g_cursor[NNODES];
__device__ int   g_row[NNODES + 1];
__device__ int   g_elist[EEDGES];
__device__ float g_ypart[OUTC * NGEMVB];
__device__ int   g_bar;

// -------------------------------------------------------------------------
// Fused CSR build: count -> barrier -> block-0 scan -> barrier -> scatter.
__global__ __launch_bounds__(256) void k_csr(const int* __restrict__ ei) {
    __shared__ int wsum[8];
    int tid = threadIdx.x;
    int bid = blockIdx.x;
    int t = bid * 256 + tid;

    if (t < NNODES) g_cursor[t] = 0;

    int4 s4 = ((const int4*)ei)[t];
    int4 d4 = ((const int4*)(ei + EEDGES))[t];
    atomicAdd(&g_deg[d4.x], 1);
    atomicAdd(&g_deg[d4.y], 1);
    atomicAdd(&g_deg[d4.z], 1);
    atomicAdd(&g_deg[d4.w], 1);

    __syncthreads();
    if (tid == 0) { __threadfence(); atomicAdd(&g_bar, 1); }

    if (bid == 0) {
        if (tid == 0) { while (*(volatile int*)&g_bar < 256) __nanosleep(20); __threadfence(); }
        __syncthreads();
        int base = tid * 32;
        int vals[32];
        {
            const int4* dp = (const int4*)&g_deg[base];
#pragma unroll
            for (int i = 0; i < 8; i++) {
                int4 v = dp[i];
                vals[i * 4 + 0] = v.x; vals[i * 4 + 1] = v.y;
                vals[i * 4 + 2] = v.z; vals[i * 4 + 3] = v.w;
            }
        }
        int s = 0;
#pragma unroll
        for (int i = 0; i < 32; i++) { int tmp = vals[i]; vals[i] = s; s += tmp; }
        int lane = tid & 31, warp = tid >> 5;
        int sc = s;
#pragma unroll
        for (int o = 1; o < 32; o <<= 1) {
            int tt = __shfl_up_sync(0xffffffffu, sc, o);
            if (lane >= o) sc += tt;
        }
        if (lane == 31) wsum[warp] = sc;
        __syncthreads();
        if (warp == 0 && lane < 8) {
            int ws = wsum[lane];
#pragma unroll
            for (int o = 1; o < 8; o <<= 1) {
                int tt = __shfl_up_sync(0xffu, ws, o);
                if (lane >= o) ws += tt;
            }
            wsum[lane] = ws;
        }
        __syncthreads();
        int off = sc - s + (warp ? wsum[warp - 1] : 0);
        {
            int4* rp = (int4*)&g_row[base];
            int4* dp = (int4*)&g_deg[base];
            int4 z = make_int4(0, 0, 0, 0);
#pragma unroll
            for (int i = 0; i < 8; i++) {
                rp[i] = make_int4(off + vals[i * 4 + 0], off + vals[i * 4 + 1],
                                  off + vals[i * 4 + 2], off + vals[i * 4 + 3]);
                dp[i] = z;
            }
        }
        if (tid == 255) g_row[NNODES] = off + s;
        __threadfence();
        __syncthreads();
        if (tid == 0) atomicAdd(&g_bar, 256);
    } else {
        if (tid == 0) { while (*(volatile int*)&g_bar < 512) __nanosleep(20); __threadfence(); }
        __syncthreads();
    }

    int p;
    p = atomicAdd(&g_cursor[d4.x], 1); g_elist[g_row[d4.x] + p] = s4.x;
    p = atomicAdd(&g_cursor[d4.y], 1); g_elist[g_row[d4.y] + p] = s4.y;
    p = atomicAdd(&g_cursor[d4.z], 1); g_elist[g_row[d4.z] + p] = s4.z;
    p = atomicAdd(&g_cursor[d4.w], 1); g_elist[g_row[d4.w] + p] = s4.w;

    __syncthreads();
    if (tid == 0) {
        __threadfence();
        int old = atomicAdd(&g_bar, 1);
        if (old == 767) atomicExch(&g_bar, 0);
    }
}

// -------------------------------------------------------------------------
// tf32 tensor-core GEMM: xh = x @ lin_w^T; epilogue writes fp32 + bf16 copies.
__device__ __forceinline__ uint32_t f2tf(float f) {
    uint32_t r;
    asm("cvt.rna.tf32.f32 %0, %1;" : "=r"(r) : "f"(f));
    return r;
}
__device__ __forceinline__ void mma_tf32(float& c0, float& c1, float& c2, float& c3,
                                         uint32_t a0, uint32_t a1, uint32_t a2, uint32_t a3,
                                         uint32_t b0, uint32_t b1) {
    asm volatile("mma.sync.aligned.m16n8k8.row.col.f32.tf32.tf32.f32 "
                 "{%0,%1,%2,%3},{%4,%5,%6,%7},{%8,%9},{%0,%1,%2,%3};"
                 : "+f"(c0), "+f"(c1), "+f"(c2), "+f"(c3)
                 : "r"(a0), "r"(a1), "r"(a2), "r"(a3), "r"(b0), "r"(b1));
}

#define GKP 36

__global__ __launch_bounds__(256) void k_gemm(const float* __restrict__ x,
                                              const float* __restrict__ w) {
    __shared__ uint32_t As[128][GKP];
    __shared__ uint32_t Bs[64][GKP];
    int tid = threadIdx.x;
    int warp = tid >> 5, lane = tid & 31;
    int g = lane >> 2, tg = lane & 3;
    int wm = warp >> 2;
    int wn = warp & 3;
    int m0 = blockIdx.x * 128;
    int n0 = blockIdx.y * 64;
    int arow = tid >> 3;
    int ac4  = tid & 7;

    float acc[4][2][4];
#pragma unroll
    for (int i = 0; i < 4; i++)
#pragma unroll
        for (int j = 0; j < 2; j++)
#pragma unroll
            for (int q = 0; q < 4; q++) acc[i][j][q] = 0.f;

    float4 pa[4], pb[2];
#pragma unroll
    for (int i = 0; i < 4; i++)
        pa[i] = *(const float4*)&x[(size_t)(m0 + arow + i * 32) * INC + ac4 * 4];
#pragma unroll
    for (int i = 0; i < 2; i++)
        pb[i] = *(const float4*)&w[(size_t)(n0 + arow + i * 32) * INC + ac4 * 4];

    for (int kt = 0; kt < 8; kt++) {
#pragma unroll
        for (int i = 0; i < 4; i++) {
            uint32_t* p = &As[arow + i * 32][ac4 * 4];
            p[0] = f2tf(pa[i].x); p[1] = f2tf(pa[i].y);
            p[2] = f2tf(pa[i].z); p[3] = f2tf(pa[i].w);
        }
#pragma unroll
        for (int i = 0; i < 2; i++) {
            uint32_t* p = &Bs[arow + i * 32][ac4 * 4];
            p[0] = f2tf(pb[i].x); p[1] = f2tf(pb[i].y);
            p[2] = f2tf(pb[i].z); p[3] = f2tf(pb[i].w);
        }
        __syncthreads();
        if (kt < 7) {
            int kb = (kt + 1) * 32;
#pragma unroll
            for (int i = 0; i < 4; i++)
                pa[i] = *(const float4*)&x[(size_t)(m0 + arow + i * 32) * INC + kb + ac4 * 4];
#pragma unroll
            for (int i = 0; i < 2; i++)
                pb[i] = *(const float4*)&w[(size_t)(n0 + arow + i * 32) * INC + kb + ac4 * 4];
        }
#pragma unroll
        for (int ks = 0; ks < 4; ks++) {
            int k0 = ks * 8;
            uint32_t af[4][4], bf[2][2];
#pragma unroll
            for (int mf = 0; mf < 4; mf++) {
                int r = wm * 64 + mf * 16 + g;
                af[mf][0] = As[r][k0 + tg];
                af[mf][1] = As[r + 8][k0 + tg];
                af[mf][2] = As[r][k0 + tg + 4];
                af[mf][3] = As[r + 8][k0 + tg + 4];
            }
#pragma unroll
            for (int nf = 0; nf < 2; nf++) {
                int cidx = wn * 16 + nf * 8 + g;
                bf[nf][0] = Bs[cidx][k0 + tg];
                bf[nf][1] = Bs[cidx][k0 + tg + 4];
            }
#pragma unroll
            for (int mf = 0; mf < 4; mf++)
#pragma unroll
                for (int nf = 0; nf < 2; nf++)
                    mma_tf32(acc[mf][nf][0], acc[mf][nf][1], acc[mf][nf][2], acc[mf][nf][3],
                             af[mf][0], af[mf][1], af[mf][2], af[mf][3],
                             bf[nf][0], bf[nf][1]);
        }
        __syncthreads();
    }
#pragma unroll
    for (int mf = 0; mf < 4; mf++) {
#pragma unroll
        for (int nf = 0; nf < 2; nf++) {
            int r = m0 + wm * 64 + mf * 16 + g;
            int c = n0 + wn * 16 + nf * 8 + tg * 2;
            *(float2*)&g_xh[(size_t)r * HCC + c] = make_float2(acc[mf][nf][0], acc[mf][nf][1]);
            *(float2*)&g_xh[(size_t)(r + 8) * HCC + c] = make_float2(acc[mf][nf][2], acc[mf][nf][3]);
            __nv_bfloat162 h0 = __float22bfloat162_rn(make_float2(acc[mf][nf][0], acc[mf][nf][1]));
            __nv_bfloat162 h1 = __float22bfloat162_rn(make_float2(acc[mf][nf][2], acc[mf][nf][3]));
            ((__nv_bfloat162*)g_xhb)[(size_t)r * (HCC/2) + c / 2] = h0;
            ((__nv_bfloat162*)g_xhb)[(size_t)(r + 8) * (HCC/2) + c / 2] = h1;
        }
    }
}

// -------------------------------------------------------------------------
// Shuffle-free attention dots: thread t handles (node, head); reads its own
// 128B row slice (coalesced across the warp), 64 FMAs vs smem att vectors.
__global__ __launch_bounds__(256) void k_attn(const float* __restrict__ att_src,
                                              const float* __restrict__ att_dst) {
    __shared__ float s_as[HCC];
    __shared__ float s_ad[HCC];
    int tid = threadIdx.x;
    s_as[tid] = att_src[tid];
    s_ad[tid] = att_dst[tid];
    __syncthreads();
    int n = blockIdx.x * 32 + (tid >> 3);
    int h = tid & 7;
    const float4* xp = (const float4*)&g_xh[(size_t)n * HCC + h * CC];
    const float4* ap = (const float4*)&s_as[h * CC];
    const float4* dp = (const float4*)&s_ad[h * CC];
    float s = 0.f, d = 0.f;
#pragma unroll
    for (int i = 0; i < 8; i++) {
        float4 v = xp[i];
        float4 a = ap[i];
        float4 b = dp[i];
        s += v.x * a.x + v.y * a.y + v.z * a.z + v.w * a.w;
        d += v.x * b.x + v.y * b.y + v.z * b.z + v.w * b.w;
    }
    g_asrc[n * HH + h] = s;
    g_adst[n * HH + h] = d;
}

// -------------------------------------------------------------------------
// Fused node aggregation (bf16 gathers) + output GEMV (fp32 streaming).
__global__ __launch_bounds__(256) void k_nodegemv(const float* __restrict__ out_w,
                                                  const float* __restrict__ bias) {
    __shared__ float4 sbuf[1024];   // 16 nodes x 256 channels (agg + bias)
    int tid = threadIdx.x;
    int warp = tid >> 5, lane = tid & 31;
    int h = lane >> 2;
    int c4 = lane * 2;
    const float4* bias4 = (const float4*)bias;
    float4 b0 = bias4[c4], b1 = bias4[c4 + 1];
    const uint4* xb = (const uint4*)g_xhb;   // 32 uint4 per node

#pragma unroll
    for (int k = 0; k < 2; k++) {
        int n = blockIdx.x * 16 + warp * 2 + k;
        int row0 = g_row[n];
        int deg = g_row[n + 1] - row0;
        float adh = __ldg(&g_adst[n * HH + h]);

        float denom;
        float4 acc0, acc1;
        { // self loop
            float v = g_asrc[n * HH + h] + adh;
            v = v > 0.f ? v : NEG * v;
            float ex = __expf(v);
            denom = ex;
            uint4 q = xb[(size_t)n * 32 + lane];
            float2 f0 = __bfloat1622float2(*(__nv_bfloat162*)&q.x);
            float2 f1 = __bfloat1622float2(*(__nv_bfloat162*)&q.y);
            float2 f2 = __bfloat1622float2(*(__nv_bfloat162*)&q.z);
            float2 f3 = __bfloat1622float2(*(__nv_bfloat162*)&q.w);
            acc0 = make_float4(ex * f0.x, ex * f0.y, ex * f1.x, ex * f1.y);
            acc1 = make_float4(ex * f2.x, ex * f2.y, ex * f3.x, ex * f3.y);
        }
#pragma unroll 8
        for (int i = 0; i < deg; i++) {
            int s = g_elist[row0 + i];
            float v = g_asrc[s * HH + h] + adh;
            v = v > 0.f ? v : NEG * v;
            float ex = __expf(v);
            denom += ex;
            uint4 q = xb[(size_t)s * 32 + lane];
            float2 f0 = __bfloat1622float2(*(__nv_bfloat162*)&q.x);
            float2 f1 = __bfloat1622float2(*(__nv_bfloat162*)&q.y);
            float2 f2 = __bfloat1622float2(*(__nv_bfloat162*)&q.z);
            float2 f3 = __bfloat1622float2(*(__nv_bfloat162*)&q.w);
            acc0.x += ex * f0.x; acc0.y += ex * f0.y; acc0.z += ex * f1.x; acc0.w += ex * f1.y;
            acc1.x += ex * f2.x; acc1.y += ex * f2.y; acc1.z += ex * f3.x; acc1.w += ex * f3.y;
        }
        float dinv = 1.f / denom;
        int ln = warp * 2 + k;
        sbuf[ln * 64 + c4]     = make_float4(acc0.x * dinv + b0.x, acc0.y * dinv + b0.y,
                                             acc0.z * dinv + b0.z, acc0.w * dinv + b0.w);
        sbuf[ln * 64 + c4 + 1] = make_float4(acc1.x * dinv + b1.x, acc1.y * dinv + b1.y,
                                             acc1.z * dinv + b1.z, acc1.w * dinv + b1.w);
    }
    __syncthreads();

    // streaming gemv: warp w -> output rows [4w, 4w+4)
    int base = blockIdx.x * 4096;
    int c0 = warp * 4;
    const float4* w0 = (const float4*)(out_w + (size_t)(c0 + 0) * FLAT + base);
    const float4* w1 = (const float4*)(out_w + (size_t)(c0 + 1) * FLAT + base);
    const float4* w2 = (const float4*)(out_w + (size_t)(c0 + 2) * FLAT + base);
    const float4* w3 = (const float4*)(out_w + (size_t)(c0 + 3) * FLAT + base);
    float a0 = 0.f, a1 = 0.f, a2 = 0.f, a3 = 0.f;
#pragma unroll 8
    for (int it = 0; it < 32; it++) {
        int idx = it * 32 + lane;
        float4 f = sbuf[idx];
        float4 v0 = __ldcs(&w0[idx]);
        float4 v1 = __ldcs(&w1[idx]);
        float4 v2 = __ldcs(&w2[idx]);
        float4 v3 = __ldcs(&w3[idx]);
        a0 += v0.x * f.x + v0.y * f.y + v0.z * f.z + v0.w * f.w;
        a1 += v1.x * f.x + v1.y * f.y + v1.z * f.z + v1.w * f.w;
        a2 += v2.x * f.x + v2.y * f.y + v2.z * f.z + v2.w * f.w;
        a3 += v3.x * f.x + v3.y * f.y + v3.z * f.z + v3.w * f.w;
    }
#pragma unroll
    for (int o = 16; o > 0; o >>= 1) {
        a0 += __shfl_xor_sync(0xffffffffu, a0, o);
        a1 += __shfl_xor_sync(0xffffffffu, a1, o);
        a2 += __shfl_xor_sync(0xffffffffu, a2, o);
        a3 += __shfl_xor_sync(0xffffffffu, a3, o);
    }
    if (lane == 0) {
        g_ypart[(size_t)(c0 + 0) * NGEMVB + blockIdx.x] = a0;
        g_ypart[(size_t)(c0 + 1) * NGEMVB + blockIdx.x] = a1;
        g_ypart[(size_t)(c0 + 2) * NGEMVB + blockIdx.x] = a2;
        g_ypart[(size_t)(c0 + 3) * NGEMVB + blockIdx.x] = a3;
    }
}

// -------------------------------------------------------------------------
__global__ __launch_bounds__(1024) void k_soft(const float* __restrict__ out_b,
                                               float* __restrict__ out) {
    __shared__ float sy[OUTC];
    int tid = threadIdx.x;
    int warp = tid >> 5, lane = tid & 31;
    float s = 0.f;
#pragma unroll
    for (int i = 0; i < NGEMVB / 32; i++)
        s += g_ypart[(size_t)warp * NGEMVB + i * 32 + lane];
#pragma unroll
    for (int o = 16; o > 0; o >>= 1) s += __shfl_xor_sync(0xffffffffu, s, o);
    if (lane == 0) sy[warp] = s + out_b[warp];
    __syncthreads();
    if (tid < 32) {
        float v = sy[tid];
        float m = v;
#pragma unroll
        for (int o = 16; o > 0; o >>= 1) m = fmaxf(m, __shfl_xor_sync(0xffffffffu, m, o));
        float ex = __expf(v - m);
        float sum = ex;
#pragma unroll
        for (int o = 16; o > 0; o >>= 1) sum += __shfl_xor_sync(0xffffffffu, sum, o);
        out[tid] = ex / sum;
    }
}

// -------------------------------------------------------------------------
extern "C" void kernel_launch(void* const* d_in, const int* in_sizes, int n_in,
                              void* d_out, int out_size) {
    const float* x       = (const float*)d_in[0];
    const int*   ei      = (const int*)d_in[1];
    const float* lin_w   = (const float*)d_in[2];
    const float* att_src = (const float*)d_in[3];
    const float* att_dst = (const float*)d_in[4];
    const float* bias    = (const float*)d_in[5];
    const float* out_w   = (const float*)d_in[6];
    const float* out_b   = (const float*)d_in[7];
    float* out = (float*)d_out;

    static cudaStream_t s2 = nullptr;
    static cudaEvent_t evFork = nullptr, evJoin = nullptr;
    if (s2 == nullptr) {
        cudaStreamCreateWithFlags(&s2, cudaStreamNonBlocking);
        cudaEventCreateWithFlags(&evFork, cudaEventDisableTiming);
        cudaEventCreateWithFlags(&evJoin, cudaEventDisableTiming);
    }

    cudaEventRecord(evFork, 0);
    // s2: fused CSR build
    cudaStreamWaitEvent(s2, evFork, 0);
    k_csr<<<256, 256, 0, s2>>>(ei);               // launch 1
    cudaEventRecord(evJoin, s2);

    // main: projection + attention dots
    k_gemm<<<dim3(NNODES / 128, HCC / 64), 256>>>(x, lin_w);   // launch 2
    k_attn<<<NNODES / 32, 256>>>(att_src, att_dst);            // launch 3

    cudaStreamWaitEvent(0, evJoin, 0);
    k_nodegemv<<<NGEMVB, 256>>>(out_w, bias);                  // launch 4 <- profiled
    k_soft<<<1, 1024>>>(out_b, out);                           // launch 5
}